// round 13
// baseline (speedup 1.0000x reference)
#include <cuda_runtime.h>
#include <cuda_fp16.h>
#include <cstdint>

// ---------------------------------------------------------------------------
// MHA block. Round 13: proj back to 128x128; attention with hoisted Q frags,
// 3 stages, 3 CTAs/SM.
// ---------------------------------------------------------------------------

#define B_   2
#define L_   2048
#define C_   1024
#define H_   16
#define DH_  64
#define QSCALE_ 0.045084439f   // 1024^-0.5 * log2(e)

// ---------------- scratch ----------------------------------------------------
__device__ __half g_x16[4096 * 1024];
__device__ __half g_wq16[3072 * 1024];
__device__ __half g_wo16[1024 * 1024];
__device__ __half g_at16[4096 * 1024];
__device__ __half g_qh[B_*H_*L_*DH_];
__device__ __half g_kh[B_*H_*L_*DH_];
__device__ __half g_vh[B_*H_*L_*DH_];

// ---------------- helpers ----------------------------------------------------
static __device__ __forceinline__ uint32_t smem_u32(const void* p) {
    uint32_t a;
    asm("{ .reg .u64 t; cvta.to.shared.u64 t, %1; cvt.u32.u64 %0, t; }"
        : "=r"(a) : "l"(p));
    return a;
}
#define SWZ(o)   ((o) ^ (((o) >> 3) & 0x70))   // 128B-row swizzle

static __device__ __forceinline__ void cp16(uint32_t saddr, const void* gaddr) {
    asm volatile("cp.async.cg.shared.global [%0], [%1], 16;"
                 :: "r"(saddr), "l"(gaddr) : "memory");
}
static __device__ __forceinline__ void ldmx4(uint32_t* r, uint32_t addr) {
    asm volatile("ldmatrix.sync.aligned.m8n8.x4.shared.b16 {%0,%1,%2,%3}, [%4];"
                 : "=r"(r[0]), "=r"(r[1]), "=r"(r[2]), "=r"(r[3]) : "r"(addr));
}
static __device__ __forceinline__ void ldmx4t(uint32_t* r, uint32_t addr) {
    asm volatile("ldmatrix.sync.aligned.m8n8.x4.trans.shared.b16 {%0,%1,%2,%3}, [%4];"
                 : "=r"(r[0]), "=r"(r[1]), "=r"(r[2]), "=r"(r[3]) : "r"(addr));
}
static __device__ __forceinline__ void mma16816h(float* c, const uint32_t* a,
                                                 const uint32_t* b) {
    asm volatile(
        "mma.sync.aligned.m16n8k16.row.col.f32.f16.f16.f32 "
        "{%0,%1,%2,%3}, {%4,%5,%6,%7}, {%8,%9}, {%0,%1,%2,%3};"
        : "+f"(c[0]), "+f"(c[1]), "+f"(c[2]), "+f"(c[3])
        : "r"(a[0]), "r"(a[1]), "r"(a[2]), "r"(a[3]), "r"(b[0]), "r"(b[1]));
}
static __device__ __forceinline__ uint32_t packh(float a, float b) {
    __half2 t = __floats2half2_rn(a, b);
    return *reinterpret_cast<uint32_t*>(&t);
}
static __device__ __forceinline__ uint32_t ex2h2(float a, float b) {
    uint32_t p = packh(a, b);
    uint32_t r;
    asm("ex2.approx.f16x2 %0, %1;" : "=r"(r) : "r"(p));
    return r;
}

// ---------------------------------------------------------------------------
// Fused fp32 -> fp16 convert: x | w_qkv | w_out, one launch (float4 units).
// ---------------------------------------------------------------------------
__global__ __launch_bounds__(256) void conv_all(const float* __restrict__ x,
                                                const float* __restrict__ wq,
                                                const float* __restrict__ wo) {
    int i = blockIdx.x * 256 + threadIdx.x;
    const float* src;
    __half* dst;
    int off;
    if (i < 1048576)       { src = x;  dst = g_x16;  off = i; }
    else if (i < 1835008)  { src = wq; dst = g_wq16; off = i - 1048576; }
    else                   { src = wo; dst = g_wo16; off = i - 1835008; }
    float4 v = reinterpret_cast<const float4*>(src)[off];
    uint2 o;
    o.x = packh(v.x, v.y);
    o.y = packh(v.z, v.w);
    *reinterpret_cast<uint2*>(dst + (size_t)off * 4) = o;
}

// ---------------------------------------------------------------------------
// fp16 HMMA GEMM: 128x128 tile, K-chunk 64 (SW128), 3-stage, 2 CTAs/SM,
// one sync per chunk. OUTK 0: QKV. OUTK 1: out-proj fp32+bias.
// ---------------------------------------------------------------------------
static constexpr int GSMEM = 98304;   // 3 stages x 32KB (A 16K | B 16K)

template <int OUTK>
__global__ __launch_bounds__(256, 2) void hmma_gemm(const float* __restrict__ bias,
                                                    float* __restrict__ outp) {
    extern __shared__ char smem[];
    const uint32_t sb = smem_u32(smem);
    const int tid = threadIdx.x;
    const int lane = tid & 31, wid = tid >> 5;
    const int wm = wid & 1, wn = wid >> 1;

    const __half* A  = (OUTK == 0) ? g_x16  : g_at16;
    const __half* Bm = (OUTK == 0) ? g_wq16 : g_wo16;

    const int n0 = blockIdx.x * 128;
    const int m0 = blockIdx.y * 128;
    const int part = (OUTK == 0) ? (blockIdx.x >> 3) : 0;     // 0=Q 1=K 2=V

    float c[4][4][4];
    #pragma unroll
    for (int i = 0; i < 4; i++)
        #pragma unroll
        for (int j = 0; j < 4; j++)
            #pragma unroll
            for (int e = 0; e < 4; e++) c[i][j][e] = 0.f;

    auto prefetch = [&](int ch) {
        const int s = ch % 3;
        const int k0 = ch * 64;
        #pragma unroll
        for (int p = 0; p < 2; p++) {
            const __half* src = p ? Bm : A;
            const int base = p ? n0 : m0;
            #pragma unroll
            for (int t = 0; t < 4; t++) {
                int idx = tid + t * 256;
                int r = idx >> 3, j = idx & 7;
                uint32_t sa = sb + s * 32768 + p * 16384 + SWZ(r * 128 + j * 16);
                cp16(sa, src + (size_t)(base + r) * 1024 + k0 + j * 8);
            }
        }
        asm volatile("cp.async.commit_group;" ::: "memory");
    };

    prefetch(0);
    prefetch(1);

    const int a_row = wm * 64 + (lane & 15);
    const int a_cb  = (lane >> 4) << 4;
    const int b_row = wn * 32 + ((lane >> 4) << 3) + (lane & 7);
    const int b_cb  = ((lane >> 3) & 1) << 4;

    for (int ch = 0; ch < 16; ch++) {
        if (ch + 1 < 16) {
            asm volatile("cp.async.wait_group 1;" ::: "memory");
        } else {
            asm volatile("cp.async.wait_group 0;" ::: "memory");
        }
        __syncthreads();
        if (ch + 2 < 16) prefetch(ch + 2);

        const uint32_t stg = sb + (ch % 3) * 32768;
        const uint32_t aS = stg, bS = stg + 16384;

        #pragma unroll
        for (int ks = 0; ks < 4; ks++) {
            const int kb = ks * 32;
            uint32_t af[4][4];
            #pragma unroll
            for (int mi = 0; mi < 4; mi++)
                ldmx4(af[mi], aS + SWZ((a_row + mi * 16) * 128 + kb + a_cb));
            uint32_t bf[4][2];
            #pragma unroll
            for (int nj = 0; nj < 2; nj++) {
                uint32_t r[4];
                ldmx4(r, bS + SWZ((b_row + nj * 16) * 128 + kb + b_cb));
                bf[nj * 2][0] = r[0]; bf[nj * 2][1] = r[1];
                bf[nj * 2 + 1][0] = r[2]; bf[nj * 2 + 1][1] = r[3];
            }
            #pragma unroll
            for (int mi = 0; mi < 4; mi++)
                #pragma unroll
                for (int nj = 0; nj < 4; nj++)
                    mma16816h(c[mi][nj], af[mi], bf[nj]);
        }
    }

    const int row_in = lane >> 2;
    const int col_in = (lane & 3) * 2;
    #pragma unroll
    for (int mi = 0; mi < 4; mi++) {
        #pragma unroll
        for (int nj = 0; nj < 4; nj++) {
            int o = n0 + wn * 32 + nj * 8 + col_in;
            #pragma unroll
            for (int half = 0; half < 2; half++) {
                int m = m0 + wm * 64 + mi * 16 + row_in + half * 8;
                float v0 = c[mi][nj][half * 2 + 0];
                float v1 = c[mi][nj][half * 2 + 1];
                if (OUTK == 0) {
                    int b = m >> 11, l = m & (L_ - 1);
                    int cc = o & (C_ - 1);
                    int hh = cc >> 6, d = cc & 63;
                    size_t base = (((size_t)(b << 4) + hh) * L_ + l) * DH_ + d;
                    if (part == 0) {
                        *reinterpret_cast<uint32_t*>(g_qh + base) =
                            packh(v0 * QSCALE_, v1 * QSCALE_);
                    } else if (part == 1) {
                        *reinterpret_cast<uint32_t*>(g_kh + base) = packh(v0, v1);
                    } else {
                        *reinterpret_cast<uint32_t*>(g_vh + base) = packh(v0, v1);
                    }
                } else {
                    float2* pd = reinterpret_cast<float2*>(outp + (size_t)m * C_ + o);
                    *pd = make_float2(v0 + bias[o], v1 + bias[o + 1]);
                }
            }
        }
    }
}

// ---------------------------------------------------------------------------
// Flash attention: 4 warps x 32 q-rows, Q frags hoisted to registers,
// fp16 base-2 softmax, 3-stage KV pipeline, 3 CTAs/SM.
// smem: Q 16K | 3 stages x 16K (K|V) = 64 KB.
// ---------------------------------------------------------------------------
static constexpr int ATT_KV   = 16384;
static constexpr int ATT_STG  = 16384;
static constexpr int ATT_SMEM = 65536;

__global__ __launch_bounds__(128, 3) void attn_mma() {
    extern __shared__ char smem[];
    const uint32_t sb = smem_u32(smem);
    const int tid = threadIdx.x, lane = tid & 31, w = tid >> 5;   // w: 0..3
    const int qt = blockIdx.x, h = blockIdx.y, b = blockIdx.z;
    const size_t bh = (size_t)(b * H_ + h) * L_;

    const int r0   = lane >> 2;
    const int cb   = (lane & 3) * 2;
    const int a_lr = lane & 15;
    const int a_cb = (lane >> 4) << 4;
    const int b_lr = ((lane >> 4) << 3) + (lane & 7);
    const int b_cb = ((lane >> 3) & 1) << 4;
    const int v_lr = (lane & 7) + (((lane >> 3) & 1) << 3);
    const int v_cB = ((lane >> 4) << 3) * 2;

    // ---- Q tile (128x64 fp16), once: 1024 float4 / 128 threads ----
    #pragma unroll
    for (int t = 0; t < 8; t++) {
        int idx = tid + t * 128;
        int r = idx >> 3, j = idx & 7;
        cp16(sb + SWZ(r * 128 + j * 16), g_qh + (bh + qt * 128 + r) * DH_ + j * 8);
    }
    asm volatile("cp.async.commit_group;" ::: "memory");

    auto prefetch = [&](int kt) {
        const uint32_t stg = sb + ATT_KV + (kt % 3) * ATT_STG;
        #pragma unroll
        for (int t = 0; t < 8; t++) {
            int idx = tid + t * 128;
            int p = idx >> 9, r = (idx >> 3) & 63, j = idx & 7;
            const __half* src = ((p == 0) ? g_kh : g_vh) + (bh + kt * 64 + r) * DH_ + j * 8;
            cp16(stg + p * 8192 + SWZ(r * 128 + j * 16), src);
        }
        asm volatile("cp.async.commit_group;" ::: "memory");
    };
    prefetch(0);
    prefetch(1);

    // ---- hoist Q fragments to registers (after Q group completes) ----
    asm volatile("cp.async.wait_group 2;" ::: "memory");   // Q done (2 KV pending)
    __syncthreads();
    uint32_t qa[2][4][4];   // [mi][ks][frag]
    #pragma unroll
    for (int mi = 0; mi < 2; mi++)
        #pragma unroll
        for (int ks = 0; ks < 4; ks++)
            ldmx4(qa[mi][ks],
                  sb + SWZ((w * 32 + mi * 16 + a_lr) * 128 + ks * 32 + a_cb));

    float c_o[2][8][4];
    #pragma unroll
    for (int mi = 0; mi < 2; mi++)
        #pragma unroll
        for (int nj = 0; nj < 8; nj++)
            #pragma unroll
            for (int e = 0; e < 4; e++) c_o[mi][nj][e] = 0.f;
    float m2[2][2] = {{-1e30f, -1e30f}, {-1e30f, -1e30f}};
    float l2[2][2] = {{0.f, 0.f}, {0.f, 0.f}};

    const int NKT = L_ / 64;
    for (int kt = 0; kt < NKT; kt++) {
        if (kt + 1 < NKT) {
            asm volatile("cp.async.wait_group 1;" ::: "memory");
        } else {
            asm volatile("cp.async.wait_group 0;" ::: "memory");
        }
        __syncthreads();
        if (kt + 2 < NKT) prefetch(kt + 2);

        const uint32_t stg = sb + ATT_KV + (kt % 3) * ATT_STG;
        const uint32_t kH = stg, vH = stg + 8192;

        // ---- S = Q K^T : warp 32x64 stripe, K frags shared across mi ----
        float c_s[2][8][4];
        #pragma unroll
        for (int mi = 0; mi < 2; mi++)
            #pragma unroll
            for (int nj = 0; nj < 8; nj++)
                #pragma unroll
                for (int e = 0; e < 4; e++) c_s[mi][nj][e] = 0.f;

        #pragma unroll
        for (int ks = 0; ks < 4; ks++) {
            const int kb = ks * 32;
            #pragma unroll
            for (int grp = 0; grp < 4; grp++) {
                uint32_t off = SWZ((grp * 16 + b_lr) * 128 + kb + b_cb);
                uint32_t r[4];
                ldmx4(r, kH + off);
                uint32_t f0[2] = {r[0], r[1]}, f1[2] = {r[2], r[3]};
                #pragma unroll
                for (int mi = 0; mi < 2; mi++) {
                    mma16816h(c_s[mi][grp * 2],     qa[mi][ks], f0);
                    mma16816h(c_s[mi][grp * 2 + 1], qa[mi][ks], f1);
                }
            }
        }

        // ---- warp-local online softmax (base 2), per mi ----
        uint32_t ph[2][4][4];
        #pragma unroll
        for (int mi = 0; mi < 2; mi++) {
            float alpha[2];
            #pragma unroll
            for (int rh = 0; rh < 2; rh++) {
                float mx = -1e30f;
                #pragma unroll
                for (int nj = 0; nj < 8; nj++)
                    mx = fmaxf(mx, fmaxf(c_s[mi][nj][rh * 2], c_s[mi][nj][rh * 2 + 1]));
                mx = fmaxf(mx, __shfl_xor_sync(0xffffffffu, mx, 1));
                mx = fmaxf(mx, __shfl_xor_sync(0xffffffffu, mx, 2));
                float mnew = fmaxf(m2[mi][rh], mx);
                alpha[rh] = exp2f(m2[mi][rh] - mnew);
                m2[mi][rh] = mnew;
            }
            float rs0 = 0.f, rs1 = 0.f;
            #pragma unroll
            for (int nj = 0; nj < 8; nj++) {
                uint32_t h01 = ex2h2(c_s[mi][nj][0] - m2[mi][0], c_s[mi][nj][1] - m2[mi][0]);
                uint32_t h23 = ex2h2(c_s[mi][nj][2] - m2[mi][1], c_s[mi][nj][3] - m2[mi][1]);
                ph[mi][nj >> 1][(nj & 1) * 2 + 0] = h01;
                ph[mi][nj >> 1][(nj & 1) * 2 + 1] = h23;
                float2 f01 = __half22float2(*reinterpret_cast<__half2*>(&h01));
                float2 f23 = __half22float2(*reinterpret_cast<__half2*>(&h23));
                rs0 += f01.x + f01.y;
                rs1 += f23.x + f23.y;
            }
            rs0 += __shfl_xor_sync(0xffffffffu, rs0, 1);
            rs0 += __shfl_xor_sync(0xffffffffu, rs0, 2);
            rs1 += __shfl_xor_sync(0xffffffffu, rs1, 1);
            rs1 += __shfl_xor_sync(0xffffffffu, rs1, 2);
            l2[mi][0] = l2[mi][0] * alpha[0] + rs0;
            l2[mi][1] = l2[mi][1] * alpha[1] + rs1;
            #pragma unroll
            for (int nj = 0; nj < 8; nj++) {
                c_o[mi][nj][0] *= alpha[0];
                c_o[mi][nj][1] *= alpha[0];
                c_o[mi][nj][2] *= alpha[1];
                c_o[mi][nj][3] *= alpha[1];
            }
        }

        // ---- O += P V : V frags shared across mi ----
        #pragma unroll
        for (int ks = 0; ks < 4; ks++) {
            uint32_t vb[8][2];
            #pragma unroll
            for (int grp = 0; grp < 4; grp++) {
                uint32_t off = SWZ((ks * 16 + v_lr) * 128 + grp * 32 + v_cB);
                uint32_t r[4];
                ldmx4t(r, vH + off);
                vb[grp * 2][0] = r[0]; vb[grp * 2][1] = r[1];
                vb[grp * 2 + 1][0] = r[2]; vb[grp * 2 + 1][1] = r[3];
            }
            #pragma unroll
            for (int mi = 0; mi < 2; mi++)
                #pragma unroll
                for (int nj = 0; nj < 8; nj++)
                    mma16816h(c_o[mi][nj], ph[mi][ks], vb[nj]);
        }
    }

    // ---- epilogue: O/l -> fp16 att ----
    #pragma unroll
    for (int mi = 0; mi < 2; mi++)
        #pragma unroll
        for (int rh = 0; rh < 2; rh++) {
            int row = qt * 128 + w * 32 + mi * 16 + r0 + rh * 8;
            float inv = 1.0f / l2[mi][rh];
            size_t grow = ((size_t)b * L_ + row) * C_ + h * DH_;
            #pragma unroll
            for (int nj = 0; nj < 8; nj++) {
                float o0 = c_o[mi][nj][rh * 2]     * inv;
                float o1 = c_o[mi][nj][rh * 2 + 1] * inv;
                *reinterpret_cast<uint32_t*>(g_at16 + grow + nj * 8 + cb) = packh(o0, o1);
            }
        }
}

// ---------------------------------------------------------------------------
extern "C" void kernel_launch(void* const* d_in, const int* in_sizes, int n_in,
                              void* d_out, int out_size) {
    const float* x     = (const float*)d_in[0];
    const float* w_qkv = (const float*)d_in[1];
    const float* w_out = (const float*)d_in[2];
    const float* b_out = (const float*)d_in[3];
    float* out = (float*)d_out;

    cudaFuncSetAttribute(hmma_gemm<0>, cudaFuncAttributeMaxDynamicSharedMemorySize, GSMEM);
    cudaFuncSetAttribute(hmma_gemm<1>, cudaFuncAttributeMaxDynamicSharedMemorySize, GSMEM);
    cudaFuncSetAttribute(attn_mma, cudaFuncAttributeMaxDynamicSharedMemorySize, ATT_SMEM);

    conv_all<<<2097152 / 256, 256>>>(x, w_qkv, w_out);

    // QKV: 24 n-tiles x 32 m-tiles (128x128)
    hmma_gemm<0><<<dim3(24, 32), 256, GSMEM>>>(nullptr, nullptr);

    // attention: 128-row q-tiles, 128 threads, 3 CTAs/SM
    attn_mma<<<dim3(L_ / 128, H_, B_), 128, ATT_SMEM>>>();

    // proj: 8 n-tiles x 32 m-tiles (128x128)
    hmma_gemm<1><<<dim3(8, 32), 256, GSMEM>>>(b_out, out);
}

// round 14
// speedup vs baseline: 1.1829x; 1.1829x over previous
#include <cuda_runtime.h>
#include <cuda_fp16.h>
#include <cstdint>

// ---------------------------------------------------------------------------
// MHA block. Round 14: round-12 attention (2 CTAs/SM, 4-stage) + Q-frag hoist
// (fits 256-reg budget); proj at 128x128.
// ---------------------------------------------------------------------------

#define B_   2
#define L_   2048
#define C_   1024
#define H_   16
#define DH_  64
#define QSCALE_ 0.045084439f   // 1024^-0.5 * log2(e)

// ---------------- scratch ----------------------------------------------------
__device__ __half g_x16[4096 * 1024];
__device__ __half g_wq16[3072 * 1024];
__device__ __half g_wo16[1024 * 1024];
__device__ __half g_at16[4096 * 1024];
__device__ __half g_qh[B_*H_*L_*DH_];
__device__ __half g_kh[B_*H_*L_*DH_];
__device__ __half g_vh[B_*H_*L_*DH_];

// ---------------- helpers ----------------------------------------------------
static __device__ __forceinline__ uint32_t smem_u32(const void* p) {
    uint32_t a;
    asm("{ .reg .u64 t; cvta.to.shared.u64 t, %1; cvt.u32.u64 %0, t; }"
        : "=r"(a) : "l"(p));
    return a;
}
#define SWZ(o)   ((o) ^ (((o) >> 3) & 0x70))   // 128B-row swizzle

static __device__ __forceinline__ void cp16(uint32_t saddr, const void* gaddr) {
    asm volatile("cp.async.cg.shared.global [%0], [%1], 16;"
                 :: "r"(saddr), "l"(gaddr) : "memory");
}
static __device__ __forceinline__ void ldmx4(uint32_t* r, uint32_t addr) {
    asm volatile("ldmatrix.sync.aligned.m8n8.x4.shared.b16 {%0,%1,%2,%3}, [%4];"
                 : "=r"(r[0]), "=r"(r[1]), "=r"(r[2]), "=r"(r[3]) : "r"(addr));
}
static __device__ __forceinline__ void ldmx4t(uint32_t* r, uint32_t addr) {
    asm volatile("ldmatrix.sync.aligned.m8n8.x4.trans.shared.b16 {%0,%1,%2,%3}, [%4];"
                 : "=r"(r[0]), "=r"(r[1]), "=r"(r[2]), "=r"(r[3]) : "r"(addr));
}
static __device__ __forceinline__ void mma16816h(float* c, const uint32_t* a,
                                                 const uint32_t* b) {
    asm volatile(
        "mma.sync.aligned.m16n8k16.row.col.f32.f16.f16.f32 "
        "{%0,%1,%2,%3}, {%4,%5,%6,%7}, {%8,%9}, {%0,%1,%2,%3};"
        : "+f"(c[0]), "+f"(c[1]), "+f"(c[2]), "+f"(c[3])
        : "r"(a[0]), "r"(a[1]), "r"(a[2]), "r"(a[3]), "r"(b[0]), "r"(b[1]));
}
static __device__ __forceinline__ uint32_t packh(float a, float b) {
    __half2 t = __floats2half2_rn(a, b);
    return *reinterpret_cast<uint32_t*>(&t);
}
static __device__ __forceinline__ uint32_t ex2h2(float a, float b) {
    uint32_t p = packh(a, b);
    uint32_t r;
    asm("ex2.approx.f16x2 %0, %1;" : "=r"(r) : "r"(p));
    return r;
}

// ---------------------------------------------------------------------------
// Fused fp32 -> fp16 convert: x | w_qkv | w_out, one launch (float4 units).
// ---------------------------------------------------------------------------
__global__ __launch_bounds__(256) void conv_all(const float* __restrict__ x,
                                                const float* __restrict__ wq,
                                                const float* __restrict__ wo) {
    int i = blockIdx.x * 256 + threadIdx.x;
    const float* src;
    __half* dst;
    int off;
    if (i < 1048576)       { src = x;  dst = g_x16;  off = i; }
    else if (i < 1835008)  { src = wq; dst = g_wq16; off = i - 1048576; }
    else                   { src = wo; dst = g_wo16; off = i - 1835008; }
    float4 v = reinterpret_cast<const float4*>(src)[off];
    uint2 o;
    o.x = packh(v.x, v.y);
    o.y = packh(v.z, v.w);
    *reinterpret_cast<uint2*>(dst + (size_t)off * 4) = o;
}

// ---------------------------------------------------------------------------
// fp16 HMMA GEMM: 128x128 tile, K-chunk 64 (SW128), 3-stage, 2 CTAs/SM,
// one sync per chunk. OUTK 0: QKV. OUTK 1: out-proj fp32+bias.
// ---------------------------------------------------------------------------
static constexpr int GSMEM = 98304;   // 3 stages x 32KB (A 16K | B 16K)

template <int OUTK>
__global__ __launch_bounds__(256, 2) void hmma_gemm(const float* __restrict__ bias,
                                                    float* __restrict__ outp) {
    extern __shared__ char smem[];
    const uint32_t sb = smem_u32(smem);
    const int tid = threadIdx.x;
    const int lane = tid & 31, wid = tid >> 5;
    const int wm = wid & 1, wn = wid >> 1;

    const __half* A  = (OUTK == 0) ? g_x16  : g_at16;
    const __half* Bm = (OUTK == 0) ? g_wq16 : g_wo16;

    const int n0 = blockIdx.x * 128;
    const int m0 = blockIdx.y * 128;
    const int part = (OUTK == 0) ? (blockIdx.x >> 3) : 0;     // 0=Q 1=K 2=V

    float c[4][4][4];
    #pragma unroll
    for (int i = 0; i < 4; i++)
        #pragma unroll
        for (int j = 0; j < 4; j++)
            #pragma unroll
            for (int e = 0; e < 4; e++) c[i][j][e] = 0.f;

    auto prefetch = [&](int ch) {
        const int s = ch % 3;
        const int k0 = ch * 64;
        #pragma unroll
        for (int p = 0; p < 2; p++) {
            const __half* src = p ? Bm : A;
            const int base = p ? n0 : m0;
            #pragma unroll
            for (int t = 0; t < 4; t++) {
                int idx = tid + t * 256;
                int r = idx >> 3, j = idx & 7;
                uint32_t sa = sb + s * 32768 + p * 16384 + SWZ(r * 128 + j * 16);
                cp16(sa, src + (size_t)(base + r) * 1024 + k0 + j * 8);
            }
        }
        asm volatile("cp.async.commit_group;" ::: "memory");
    };

    prefetch(0);
    prefetch(1);

    const int a_row = wm * 64 + (lane & 15);
    const int a_cb  = (lane >> 4) << 4;
    const int b_row = wn * 32 + ((lane >> 4) << 3) + (lane & 7);
    const int b_cb  = ((lane >> 3) & 1) << 4;

    for (int ch = 0; ch < 16; ch++) {
        if (ch + 1 < 16) {
            asm volatile("cp.async.wait_group 1;" ::: "memory");
        } else {
            asm volatile("cp.async.wait_group 0;" ::: "memory");
        }
        __syncthreads();
        if (ch + 2 < 16) prefetch(ch + 2);

        const uint32_t stg = sb + (ch % 3) * 32768;
        const uint32_t aS = stg, bS = stg + 16384;

        #pragma unroll
        for (int ks = 0; ks < 4; ks++) {
            const int kb = ks * 32;
            uint32_t af[4][4];
            #pragma unroll
            for (int mi = 0; mi < 4; mi++)
                ldmx4(af[mi], aS + SWZ((a_row + mi * 16) * 128 + kb + a_cb));
            uint32_t bf[4][2];
            #pragma unroll
            for (int nj = 0; nj < 2; nj++) {
                uint32_t r[4];
                ldmx4(r, bS + SWZ((b_row + nj * 16) * 128 + kb + b_cb));
                bf[nj * 2][0] = r[0]; bf[nj * 2][1] = r[1];
                bf[nj * 2 + 1][0] = r[2]; bf[nj * 2 + 1][1] = r[3];
            }
            #pragma unroll
            for (int mi = 0; mi < 4; mi++)
                #pragma unroll
                for (int nj = 0; nj < 4; nj++)
                    mma16816h(c[mi][nj], af[mi], bf[nj]);
        }
    }

    const int row_in = lane >> 2;
    const int col_in = (lane & 3) * 2;
    #pragma unroll
    for (int mi = 0; mi < 4; mi++) {
        #pragma unroll
        for (int nj = 0; nj < 4; nj++) {
            int o = n0 + wn * 32 + nj * 8 + col_in;
            #pragma unroll
            for (int half = 0; half < 2; half++) {
                int m = m0 + wm * 64 + mi * 16 + row_in + half * 8;
                float v0 = c[mi][nj][half * 2 + 0];
                float v1 = c[mi][nj][half * 2 + 1];
                if (OUTK == 0) {
                    int b = m >> 11, l = m & (L_ - 1);
                    int cc = o & (C_ - 1);
                    int hh = cc >> 6, d = cc & 63;
                    size_t base = (((size_t)(b << 4) + hh) * L_ + l) * DH_ + d;
                    if (part == 0) {
                        *reinterpret_cast<uint32_t*>(g_qh + base) =
                            packh(v0 * QSCALE_, v1 * QSCALE_);
                    } else if (part == 1) {
                        *reinterpret_cast<uint32_t*>(g_kh + base) = packh(v0, v1);
                    } else {
                        *reinterpret_cast<uint32_t*>(g_vh + base) = packh(v0, v1);
                    }
                } else {
                    float2* pd = reinterpret_cast<float2*>(outp + (size_t)m * C_ + o);
                    *pd = make_float2(v0 + bias[o], v1 + bias[o + 1]);
                }
            }
        }
    }
}

// ---------------------------------------------------------------------------
// Flash attention: 4 warps x 32 q-rows, Q frags hoisted to registers,
// fp16 base-2 softmax, 4-stage KV pipeline, 2 CTAs/SM (256-reg budget).
// smem: Q 16K | 4 stages x 16K (K|V) = 80 KB.
// ---------------------------------------------------------------------------
static constexpr int ATT_KV   = 16384;
static constexpr int ATT_STG  = 16384;
static constexpr int ATT_SMEM = 81920;

__global__ __launch_bounds__(128, 2) void attn_mma() {
    extern __shared__ char smem[];
    const uint32_t sb = smem_u32(smem);
    const int tid = threadIdx.x, lane = tid & 31, w = tid >> 5;   // w: 0..3
    const int qt = blockIdx.x, h = blockIdx.y, b = blockIdx.z;
    const size_t bh = (size_t)(b * H_ + h) * L_;

    const int r0   = lane >> 2;
    const int cb   = (lane & 3) * 2;
    const int a_lr = lane & 15;
    const int a_cb = (lane >> 4) << 4;
    const int b_lr = ((lane >> 4) << 3) + (lane & 7);
    const int b_cb = ((lane >> 3) & 1) << 4;
    const int v_lr = (lane & 7) + (((lane >> 3) & 1) << 3);
    const int v_cB = ((lane >> 4) << 3) * 2;

    // ---- Q tile (128x64 fp16), once: 1024 float4 / 128 threads ----
    #pragma unroll
    for (int t = 0; t < 8; t++) {
        int idx = tid + t * 128;
        int r = idx >> 3, j = idx & 7;
        cp16(sb + SWZ(r * 128 + j * 16), g_qh + (bh + qt * 128 + r) * DH_ + j * 8);
    }
    asm volatile("cp.async.commit_group;" ::: "memory");

    auto prefetch = [&](int kt) {
        const uint32_t stg = sb + ATT_KV + (kt & 3) * ATT_STG;
        #pragma unroll
        for (int t = 0; t < 8; t++) {
            int idx = tid + t * 128;
            int p = idx >> 9, r = (idx >> 3) & 63, j = idx & 7;
            const __half* src = ((p == 0) ? g_kh : g_vh) + (bh + kt * 64 + r) * DH_ + j * 8;
            cp16(stg + p * 8192 + SWZ(r * 128 + j * 16), src);
        }
        asm volatile("cp.async.commit_group;" ::: "memory");
    };
    prefetch(0);
    prefetch(1);
    prefetch(2);

    // ---- hoist Q fragments to registers (after Q group completes) ----
    asm volatile("cp.async.wait_group 3;" ::: "memory");   // Q done (3 KV pending)
    __syncthreads();
    uint32_t qa[2][4][4];   // [mi][ks][frag]
    #pragma unroll
    for (int mi = 0; mi < 2; mi++)
        #pragma unroll
        for (int ks = 0; ks < 4; ks++)
            ldmx4(qa[mi][ks],
                  sb + SWZ((w * 32 + mi * 16 + a_lr) * 128 + ks * 32 + a_cb));

    float c_o[2][8][4];
    #pragma unroll
    for (int mi = 0; mi < 2; mi++)
        #pragma unroll
        for (int nj = 0; nj < 8; nj++)
            #pragma unroll
            for (int e = 0; e < 4; e++) c_o[mi][nj][e] = 0.f;
    float m2[2][2] = {{-1e30f, -1e30f}, {-1e30f, -1e30f}};
    float l2[2][2] = {{0.f, 0.f}, {0.f, 0.f}};

    const int NKT = L_ / 64;
    for (int kt = 0; kt < NKT; kt++) {
        int inflight = (NKT - 1 - kt < 2) ? (NKT - 1 - kt) : 2;
        if (inflight == 2) {
            asm volatile("cp.async.wait_group 2;" ::: "memory");
        } else if (inflight == 1) {
            asm volatile("cp.async.wait_group 1;" ::: "memory");
        } else {
            asm volatile("cp.async.wait_group 0;" ::: "memory");
        }
        __syncthreads();
        if (kt + 3 < NKT) prefetch(kt + 3);

        const uint32_t stg = sb + ATT_KV + (kt & 3) * ATT_STG;
        const uint32_t kH = stg, vH = stg + 8192;

        // ---- S = Q K^T : warp 32x64 stripe, K frags shared across mi ----
        float c_s[2][8][4];
        #pragma unroll
        for (int mi = 0; mi < 2; mi++)
            #pragma unroll
            for (int nj = 0; nj < 8; nj++)
                #pragma unroll
                for (int e = 0; e < 4; e++) c_s[mi][nj][e] = 0.f;

        #pragma unroll
        for (int ks = 0; ks < 4; ks++) {
            const int kb = ks * 32;
            #pragma unroll
            for (int grp = 0; grp < 4; grp++) {
                uint32_t off = SWZ((grp * 16 + b_lr) * 128 + kb + b_cb);
                uint32_t r[4];
                ldmx4(r, kH + off);
                uint32_t f0[2] = {r[0], r[1]}, f1[2] = {r[2], r[3]};
                #pragma unroll
                for (int mi = 0; mi < 2; mi++) {
                    mma16816h(c_s[mi][grp * 2],     qa[mi][ks], f0);
                    mma16816h(c_s[mi][grp * 2 + 1], qa[mi][ks], f1);
                }
            }
        }

        // ---- warp-local online softmax (base 2), per mi ----
        uint32_t ph[2][4][4];
        #pragma unroll
        for (int mi = 0; mi < 2; mi++) {
            float alpha[2];
            #pragma unroll
            for (int rh = 0; rh < 2; rh++) {
                float mx = -1e30f;
                #pragma unroll
                for (int nj = 0; nj < 8; nj++)
                    mx = fmaxf(mx, fmaxf(c_s[mi][nj][rh * 2], c_s[mi][nj][rh * 2 + 1]));
                mx = fmaxf(mx, __shfl_xor_sync(0xffffffffu, mx, 1));
                mx = fmaxf(mx, __shfl_xor_sync(0xffffffffu, mx, 2));
                float mnew = fmaxf(m2[mi][rh], mx);
                alpha[rh] = exp2f(m2[mi][rh] - mnew);
                m2[mi][rh] = mnew;
            }
            float rs0 = 0.f, rs1 = 0.f;
            #pragma unroll
            for (int nj = 0; nj < 8; nj++) {
                uint32_t h01 = ex2h2(c_s[mi][nj][0] - m2[mi][0], c_s[mi][nj][1] - m2[mi][0]);
                uint32_t h23 = ex2h2(c_s[mi][nj][2] - m2[mi][1], c_s[mi][nj][3] - m2[mi][1]);
                ph[mi][nj >> 1][(nj & 1) * 2 + 0] = h01;
                ph[mi][nj >> 1][(nj & 1) * 2 + 1] = h23;
                float2 f01 = __half22float2(*reinterpret_cast<__half2*>(&h01));
                float2 f23 = __half22float2(*reinterpret_cast<__half2*>(&h23));
                rs0 += f01.x + f01.y;
                rs1 += f23.x + f23.y;
            }
            rs0 += __shfl_xor_sync(0xffffffffu, rs0, 1);
            rs0 += __shfl_xor_sync(0xffffffffu, rs0, 2);
            rs1 += __shfl_xor_sync(0xffffffffu, rs1, 1);
            rs1 += __shfl_xor_sync(0xffffffffu, rs1, 2);
            l2[mi][0] = l2[mi][0] * alpha[0] + rs0;
            l2[mi][1] = l2[mi][1] * alpha[1] + rs1;
            #pragma unroll
            for (int nj = 0; nj < 8; nj++) {
                c_o[mi][nj][0] *= alpha[0];
                c_o[mi][nj][1] *= alpha[0];
                c_o[mi][nj][2] *= alpha[1];
                c_o[mi][nj][3] *= alpha[1];
            }
        }

        // ---- O += P V : V frags shared across mi ----
        #pragma unroll
        for (int ks = 0; ks < 4; ks++) {
            uint32_t vb[8][2];
            #pragma unroll
            for (int grp = 0; grp < 4; grp++) {
                uint32_t off = SWZ((ks * 16 + v_lr) * 128 + grp * 32 + v_cB);
                uint32_t r[4];
                ldmx4t(r, vH + off);
                vb[grp * 2][0] = r[0]; vb[grp * 2][1] = r[1];
                vb[grp * 2 + 1][0] = r[2]; vb[grp * 2 + 1][1] = r[3];
            }
            #pragma unroll
            for (int mi = 0; mi < 2; mi++)
                #pragma unroll
                for (int nj = 0; nj < 8; nj++)
                    mma16816h(c_o[mi][nj], ph[mi][ks], vb[nj]);
        }
    }

    // ---- epilogue: O/l -> fp16 att ----
    #pragma unroll
    for (int mi = 0; mi < 2; mi++)
        #pragma unroll
        for (int rh = 0; rh < 2; rh++) {
            int row = qt * 128 + w * 32 + mi * 16 + r0 + rh * 8;
            float inv = 1.0f / l2[mi][rh];
            size_t grow = ((size_t)b * L_ + row) * C_ + h * DH_;
            #pragma unroll
            for (int nj = 0; nj < 8; nj++) {
                float o0 = c_o[mi][nj][rh * 2]     * inv;
                float o1 = c_o[mi][nj][rh * 2 + 1] * inv;
                *reinterpret_cast<uint32_t*>(g_at16 + grow + nj * 8 + cb) = packh(o0, o1);
            }
        }
}

// ---------------------------------------------------------------------------
extern "C" void kernel_launch(void* const* d_in, const int* in_sizes, int n_in,
                              void* d_out, int out_size) {
    const float* x     = (const float*)d_in[0];
    const float* w_qkv = (const float*)d_in[1];
    const float* w_out = (const float*)d_in[2];
    const float* b_out = (const float*)d_in[3];
    float* out = (float*)d_out;

    cudaFuncSetAttribute(hmma_gemm<0>, cudaFuncAttributeMaxDynamicSharedMemorySize, GSMEM);
    cudaFuncSetAttribute(hmma_gemm<1>, cudaFuncAttributeMaxDynamicSharedMemorySize, GSMEM);
    cudaFuncSetAttribute(attn_mma, cudaFuncAttributeMaxDynamicSharedMemorySize, ATT_SMEM);

    conv_all<<<2097152 / 256, 256>>>(x, w_qkv, w_out);

    // QKV: 24 n-tiles x 32 m-tiles (128x128)
    hmma_gemm<0><<<dim3(24, 32), 256, GSMEM>>>(nullptr, nullptr);

    // attention: 128-row q-tiles, 128 threads, 2 CTAs/SM
    attn_mma<<<dim3(L_ / 128, H_, B_), 128, ATT_SMEM>>>();

    // proj: 8 n-tiles x 32 m-tiles (128x128)
    hmma_gemm<1><<<dim3(8, 32), 256, GSMEM>>>(b_out, out);
}

// round 15
// speedup vs baseline: 1.2513x; 1.0578x over previous
#include <cuda_runtime.h>
#include <cuda_fp16.h>
#include <cstdint>

// ---------------------------------------------------------------------------
// MHA block. Round 15: attention S accum in fp16, softmax fully in half2
// domain (S frags become PV frags in place). GEMMs as round 14.
// ---------------------------------------------------------------------------

#define B_   2
#define L_   2048
#define C_   1024
#define H_   16
#define DH_  64
#define QSCALE_ 0.045084439f   // 1024^-0.5 * log2(e)

// ---------------- scratch ----------------------------------------------------
__device__ __half g_x16[4096 * 1024];
__device__ __half g_wq16[3072 * 1024];
__device__ __half g_wo16[1024 * 1024];
__device__ __half g_at16[4096 * 1024];
__device__ __half g_qh[B_*H_*L_*DH_];
__device__ __half g_kh[B_*H_*L_*DH_];
__device__ __half g_vh[B_*H_*L_*DH_];

// ---------------- helpers ----------------------------------------------------
static __device__ __forceinline__ uint32_t smem_u32(const void* p) {
    uint32_t a;
    asm("{ .reg .u64 t; cvta.to.shared.u64 t, %1; cvt.u32.u64 %0, t; }"
        : "=r"(a) : "l"(p));
    return a;
}
#define SWZ(o)   ((o) ^ (((o) >> 3) & 0x70))   // 128B-row swizzle

static __device__ __forceinline__ void cp16(uint32_t saddr, const void* gaddr) {
    asm volatile("cp.async.cg.shared.global [%0], [%1], 16;"
                 :: "r"(saddr), "l"(gaddr) : "memory");
}
static __device__ __forceinline__ void ldmx4(uint32_t* r, uint32_t addr) {
    asm volatile("ldmatrix.sync.aligned.m8n8.x4.shared.b16 {%0,%1,%2,%3}, [%4];"
                 : "=r"(r[0]), "=r"(r[1]), "=r"(r[2]), "=r"(r[3]) : "r"(addr));
}
static __device__ __forceinline__ void ldmx4t(uint32_t* r, uint32_t addr) {
    asm volatile("ldmatrix.sync.aligned.m8n8.x4.trans.shared.b16 {%0,%1,%2,%3}, [%4];"
                 : "=r"(r[0]), "=r"(r[1]), "=r"(r[2]), "=r"(r[3]) : "r"(addr));
}
static __device__ __forceinline__ void mma16816h(float* c, const uint32_t* a,
                                                 const uint32_t* b) {
    asm volatile(
        "mma.sync.aligned.m16n8k16.row.col.f32.f16.f16.f32 "
        "{%0,%1,%2,%3}, {%4,%5,%6,%7}, {%8,%9}, {%0,%1,%2,%3};"
        : "+f"(c[0]), "+f"(c[1]), "+f"(c[2]), "+f"(c[3])
        : "r"(a[0]), "r"(a[1]), "r"(a[2]), "r"(a[3]), "r"(b[0]), "r"(b[1]));
}
// fp16-accumulator MMA (for S)
static __device__ __forceinline__ void mma16816hh(uint32_t* d, const uint32_t* a,
                                                  const uint32_t* b) {
    asm volatile(
        "mma.sync.aligned.m16n8k16.row.col.f16.f16.f16.f16 "
        "{%0,%1}, {%2,%3,%4,%5}, {%6,%7}, {%0,%1};"
        : "+r"(d[0]), "+r"(d[1])
        : "r"(a[0]), "r"(a[1]), "r"(a[2]), "r"(a[3]), "r"(b[0]), "r"(b[1]));
}
static __device__ __forceinline__ uint32_t packh(float a, float b) {
    __half2 t = __floats2half2_rn(a, b);
    return *reinterpret_cast<uint32_t*>(&t);
}
static __device__ __forceinline__ uint32_t ex2u(uint32_t p) {
    uint32_t r;
    asm("ex2.approx.f16x2 %0, %1;" : "=r"(r) : "r"(p));
    return r;
}
static __device__ __forceinline__ __half2 u2h(uint32_t u) {
    return *reinterpret_cast<__half2*>(&u);
}
static __device__ __forceinline__ uint32_t h2u(__half2 h) {
    return *reinterpret_cast<uint32_t*>(&h);
}

// ---------------------------------------------------------------------------
// Fused fp32 -> fp16 convert: x | w_qkv | w_out, one launch (float4 units).
// ---------------------------------------------------------------------------
__global__ __launch_bounds__(256) void conv_all(const float* __restrict__ x,
                                                const float* __restrict__ wq,
                                                const float* __restrict__ wo) {
    int i = blockIdx.x * 256 + threadIdx.x;
    const float* src;
    __half* dst;
    int off;
    if (i < 1048576)       { src = x;  dst = g_x16;  off = i; }
    else if (i < 1835008)  { src = wq; dst = g_wq16; off = i - 1048576; }
    else                   { src = wo; dst = g_wo16; off = i - 1835008; }
    float4 v = reinterpret_cast<const float4*>(src)[off];
    uint2 o;
    o.x = packh(v.x, v.y);
    o.y = packh(v.z, v.w);
    *reinterpret_cast<uint2*>(dst + (size_t)off * 4) = o;
}

// ---------------------------------------------------------------------------
// fp16 HMMA GEMM: 128x128 tile, K-chunk 64 (SW128), 3-stage, 2 CTAs/SM,
// one sync per chunk. OUTK 0: QKV. OUTK 1: out-proj fp32+bias.
// ---------------------------------------------------------------------------
static constexpr int GSMEM = 98304;   // 3 stages x 32KB (A 16K | B 16K)

template <int OUTK>
__global__ __launch_bounds__(256, 2) void hmma_gemm(const float* __restrict__ bias,
                                                    float* __restrict__ outp) {
    extern __shared__ char smem[];
    const uint32_t sb = smem_u32(smem);
    const int tid = threadIdx.x;
    const int lane = tid & 31, wid = tid >> 5;
    const int wm = wid & 1, wn = wid >> 1;

    const __half* A  = (OUTK == 0) ? g_x16  : g_at16;
    const __half* Bm = (OUTK == 0) ? g_wq16 : g_wo16;

    const int n0 = blockIdx.x * 128;
    const int m0 = blockIdx.y * 128;
    const int part = (OUTK == 0) ? (blockIdx.x >> 3) : 0;     // 0=Q 1=K 2=V

    float c[4][4][4];
    #pragma unroll
    for (int i = 0; i < 4; i++)
        #pragma unroll
        for (int j = 0; j < 4; j++)
            #pragma unroll
            for (int e = 0; e < 4; e++) c[i][j][e] = 0.f;

    auto prefetch = [&](int ch) {
        const int s = ch % 3;
        const int k0 = ch * 64;
        #pragma unroll
        for (int p = 0; p < 2; p++) {
            const __half* src = p ? Bm : A;
            const int base = p ? n0 : m0;
            #pragma unroll
            for (int t = 0; t < 4; t++) {
                int idx = tid + t * 256;
                int r = idx >> 3, j = idx & 7;
                uint32_t sa = sb + s * 32768 + p * 16384 + SWZ(r * 128 + j * 16);
                cp16(sa, src + (size_t)(base + r) * 1024 + k0 + j * 8);
            }
        }
        asm volatile("cp.async.commit_group;" ::: "memory");
    };

    prefetch(0);
    prefetch(1);

    const int a_row = wm * 64 + (lane & 15);
    const int a_cb  = (lane >> 4) << 4;
    const int b_row = wn * 32 + ((lane >> 4) << 3) + (lane & 7);
    const int b_cb  = ((lane >> 3) & 1) << 4;

    for (int ch = 0; ch < 16; ch++) {
        if (ch + 1 < 16) {
            asm volatile("cp.async.wait_group 1;" ::: "memory");
        } else {
            asm volatile("cp.async.wait_group 0;" ::: "memory");
        }
        __syncthreads();
        if (ch + 2 < 16) prefetch(ch + 2);

        const uint32_t stg = sb + (ch % 3) * 32768;
        const uint32_t aS = stg, bS = stg + 16384;

        #pragma unroll
        for (int ks = 0; ks < 4; ks++) {
            const int kb = ks * 32;
            uint32_t af[4][4];
            #pragma unroll
            for (int mi = 0; mi < 4; mi++)
                ldmx4(af[mi], aS + SWZ((a_row + mi * 16) * 128 + kb + a_cb));
            uint32_t bf[4][2];
            #pragma unroll
            for (int nj = 0; nj < 2; nj++) {
                uint32_t r[4];
                ldmx4(r, bS + SWZ((b_row + nj * 16) * 128 + kb + b_cb));
                bf[nj * 2][0] = r[0]; bf[nj * 2][1] = r[1];
                bf[nj * 2 + 1][0] = r[2]; bf[nj * 2 + 1][1] = r[3];
            }
            #pragma unroll
            for (int mi = 0; mi < 4; mi++)
                #pragma unroll
                for (int nj = 0; nj < 4; nj++)
                    mma16816h(c[mi][nj], af[mi], bf[nj]);
        }
    }

    const int row_in = lane >> 2;
    const int col_in = (lane & 3) * 2;
    #pragma unroll
    for (int mi = 0; mi < 4; mi++) {
        #pragma unroll
        for (int nj = 0; nj < 4; nj++) {
            int o = n0 + wn * 32 + nj * 8 + col_in;
            #pragma unroll
            for (int half = 0; half < 2; half++) {
                int m = m0 + wm * 64 + mi * 16 + row_in + half * 8;
                float v0 = c[mi][nj][half * 2 + 0];
                float v1 = c[mi][nj][half * 2 + 1];
                if (OUTK == 0) {
                    int b = m >> 11, l = m & (L_ - 1);
                    int cc = o & (C_ - 1);
                    int hh = cc >> 6, d = cc & 63;
                    size_t base = (((size_t)(b << 4) + hh) * L_ + l) * DH_ + d;
                    if (part == 0) {
                        *reinterpret_cast<uint32_t*>(g_qh + base) =
                            packh(v0 * QSCALE_, v1 * QSCALE_);
                    } else if (part == 1) {
                        *reinterpret_cast<uint32_t*>(g_kh + base) = packh(v0, v1);
                    } else {
                        *reinterpret_cast<uint32_t*>(g_vh + base) = packh(v0, v1);
                    }
                } else {
                    float2* pd = reinterpret_cast<float2*>(outp + (size_t)m * C_ + o);
                    *pd = make_float2(v0 + bias[o], v1 + bias[o + 1]);
                }
            }
        }
    }
}

// ---------------------------------------------------------------------------
// Flash attention: 4 warps x 32 q-rows, Q frags in registers, S accum fp16,
// softmax in half2 (S frags transform in place into PV frags).
// 4-stage KV pipeline, 2 CTAs/SM. smem: Q 16K | 4 x 16K = 80 KB.
// ---------------------------------------------------------------------------
static constexpr int ATT_KV   = 16384;
static constexpr int ATT_STG  = 16384;
static constexpr int ATT_SMEM = 81920;

__global__ __launch_bounds__(128, 2) void attn_mma() {
    extern __shared__ char smem[];
    const uint32_t sb = smem_u32(smem);
    const int tid = threadIdx.x, lane = tid & 31, w = tid >> 5;   // w: 0..3
    const int qt = blockIdx.x, h = blockIdx.y, b = blockIdx.z;
    const size_t bh = (size_t)(b * H_ + h) * L_;

    const int r0   = lane >> 2;
    const int cb   = (lane & 3) * 2;
    const int a_lr = lane & 15;
    const int a_cb = (lane >> 4) << 4;
    const int b_lr = ((lane >> 4) << 3) + (lane & 7);
    const int b_cb = ((lane >> 3) & 1) << 4;
    const int v_lr = (lane & 7) + (((lane >> 3) & 1) << 3);
    const int v_cB = ((lane >> 4) << 3) * 2;

    // ---- Q tile (128x64 fp16), once ----
    #pragma unroll
    for (int t = 0; t < 8; t++) {
        int idx = tid + t * 128;
        int r = idx >> 3, j = idx & 7;
        cp16(sb + SWZ(r * 128 + j * 16), g_qh + (bh + qt * 128 + r) * DH_ + j * 8);
    }
    asm volatile("cp.async.commit_group;" ::: "memory");

    auto prefetch = [&](int kt) {
        const uint32_t stg = sb + ATT_KV + (kt & 3) * ATT_STG;
        #pragma unroll
        for (int t = 0; t < 8; t++) {
            int idx = tid + t * 128;
            int p = idx >> 9, r = (idx >> 3) & 63, j = idx & 7;
            const __half* src = ((p == 0) ? g_kh : g_vh) + (bh + kt * 64 + r) * DH_ + j * 8;
            cp16(stg + p * 8192 + SWZ(r * 128 + j * 16), src);
        }
        asm volatile("cp.async.commit_group;" ::: "memory");
    };
    prefetch(0);
    prefetch(1);
    prefetch(2);

    // ---- hoist Q fragments to registers ----
    asm volatile("cp.async.wait_group 3;" ::: "memory");   // Q done (3 KV pending)
    __syncthreads();
    uint32_t qa[2][4][4];   // [mi][ks][frag]
    #pragma unroll
    for (int mi = 0; mi < 2; mi++)
        #pragma unroll
        for (int ks = 0; ks < 4; ks++)
            ldmx4(qa[mi][ks],
                  sb + SWZ((w * 32 + mi * 16 + a_lr) * 128 + ks * 32 + a_cb));

    float c_o[2][8][4];
    #pragma unroll
    for (int mi = 0; mi < 2; mi++)
        #pragma unroll
        for (int nj = 0; nj < 8; nj++)
            #pragma unroll
            for (int e = 0; e < 4; e++) c_o[mi][nj][e] = 0.f;
    float m2[2][2] = {{-1e30f, -1e30f}, {-1e30f, -1e30f}};
    float l2[2][2] = {{0.f, 0.f}, {0.f, 0.f}};

    const int NKT = L_ / 64;
    for (int kt = 0; kt < NKT; kt++) {
        int inflight = (NKT - 1 - kt < 2) ? (NKT - 1 - kt) : 2;
        if (inflight == 2) {
            asm volatile("cp.async.wait_group 2;" ::: "memory");
        } else if (inflight == 1) {
            asm volatile("cp.async.wait_group 1;" ::: "memory");
        } else {
            asm volatile("cp.async.wait_group 0;" ::: "memory");
        }
        __syncthreads();
        if (kt + 3 < NKT) prefetch(kt + 3);

        const uint32_t stg = sb + ATT_KV + (kt & 3) * ATT_STG;
        const uint32_t kH = stg, vH = stg + 8192;

        // ---- S = Q K^T : fp16 accumulators.
        //      sp[mi][nj][rh]: half2 of cols (nj*8+cb, +1), rows r0 + rh*8. ----
        uint32_t sp[2][8][2];
        #pragma unroll
        for (int mi = 0; mi < 2; mi++)
            #pragma unroll
            for (int nj = 0; nj < 8; nj++)
                sp[mi][nj][0] = sp[mi][nj][1] = 0u;

        #pragma unroll
        for (int ks = 0; ks < 4; ks++) {
            const int kb = ks * 32;
            #pragma unroll
            for (int grp = 0; grp < 4; grp++) {
                uint32_t off = SWZ((grp * 16 + b_lr) * 128 + kb + b_cb);
                uint32_t r[4];
                ldmx4(r, kH + off);
                uint32_t f0[2] = {r[0], r[1]}, f1[2] = {r[2], r[3]};
                #pragma unroll
                for (int mi = 0; mi < 2; mi++) {
                    mma16816hh(sp[mi][grp * 2],     qa[mi][ks], f0);
                    mma16816hh(sp[mi][grp * 2 + 1], qa[mi][ks], f1);
                }
            }
        }

        // ---- half2 online softmax; sp transforms in place into P frags ----
        #pragma unroll
        for (int mi = 0; mi < 2; mi++) {
            #pragma unroll
            for (int rh = 0; rh < 2; rh++) {
                // row max over 16 cols (8 half2 regs)
                __half2 mx2 = u2h(sp[mi][0][rh]);
                #pragma unroll
                for (int nj = 1; nj < 8; nj++)
                    mx2 = __hmax2(mx2, u2h(sp[mi][nj][rh]));
                float mx = fmaxf(__low2float(mx2), __high2float(mx2));
                mx = fmaxf(mx, __shfl_xor_sync(0xffffffffu, mx, 1));
                mx = fmaxf(mx, __shfl_xor_sync(0xffffffffu, mx, 2));
                float mnew = fmaxf(m2[mi][rh], mx);
                float alpha = exp2f(m2[mi][rh] - mnew);
                m2[mi][rh] = mnew;

                // P = 2^(s - m) in place; row sum in half2
                __half2 mh = __float2half2_rn(mnew);
                __half2 ssum = __float2half2_rn(0.f);
                #pragma unroll
                for (int nj = 0; nj < 8; nj++) {
                    uint32_t e = ex2u(h2u(__hsub2(u2h(sp[mi][nj][rh]), mh)));
                    sp[mi][nj][rh] = e;
                    ssum = __hadd2(ssum, u2h(e));
                }
                float rs = __low2float(ssum) + __high2float(ssum);
                rs += __shfl_xor_sync(0xffffffffu, rs, 1);
                rs += __shfl_xor_sync(0xffffffffu, rs, 2);
                l2[mi][rh] = l2[mi][rh] * alpha + rs;
                #pragma unroll
                for (int nj = 0; nj < 8; nj++) {
                    c_o[mi][nj][rh * 2]     *= alpha;
                    c_o[mi][nj][rh * 2 + 1] *= alpha;
                }
            }
        }

        // ---- O += P V : sp IS the A-fragment set ----
        #pragma unroll
        for (int ks = 0; ks < 4; ks++) {
            uint32_t vb[8][2];
            #pragma unroll
            for (int grp = 0; grp < 4; grp++) {
                uint32_t off = SWZ((ks * 16 + v_lr) * 128 + grp * 32 + v_cB);
                uint32_t r[4];
                ldmx4t(r, vH + off);
                vb[grp * 2][0] = r[0]; vb[grp * 2][1] = r[1];
                vb[grp * 2 + 1][0] = r[2]; vb[grp * 2 + 1][1] = r[3];
            }
            #pragma unroll
            for (int mi = 0; mi < 2; mi++) {
                uint32_t pa[4] = {sp[mi][ks * 2][0], sp[mi][ks * 2][1],
                                  sp[mi][ks * 2 + 1][0], sp[mi][ks * 2 + 1][1]};
                #pragma unroll
                for (int nj = 0; nj < 8; nj++)
                    mma16816h(c_o[mi][nj], pa, vb[nj]);
            }
        }
    }

    // ---- epilogue: O/l -> fp16 att ----
    #pragma unroll
    for (int mi = 0; mi < 2; mi++)
        #pragma unroll
        for (int rh = 0; rh < 2; rh++) {
            int row = qt * 128 + w * 32 + mi * 16 + r0 + rh * 8;
            float inv = 1.0f / l2[mi][rh];
            size_t grow = ((size_t)b * L_ + row) * C_ + h * DH_;
            #pragma unroll
            for (int nj = 0; nj < 8; nj++) {
                float o0 = c_o[mi][nj][rh * 2]     * inv;
                float o1 = c_o[mi][nj][rh * 2 + 1] * inv;
                *reinterpret_cast<uint32_t*>(g_at16 + grow + nj * 8 + cb) = packh(o0, o1);
            }
        }
}

// ---------------------------------------------------------------------------
extern "C" void kernel_launch(void* const* d_in, const int* in_sizes, int n_in,
                              void* d_out, int out_size) {
    const float* x     = (const float*)d_in[0];
    const float* w_qkv = (const float*)d_in[1];
    const float* w_out = (const float*)d_in[2];
    const float* b_out = (const float*)d_in[3];
    float* out = (float*)d_out;

    cudaFuncSetAttribute(hmma_gemm<0>, cudaFuncAttributeMaxDynamicSharedMemorySize, GSMEM);
    cudaFuncSetAttribute(hmma_gemm<1>, cudaFuncAttributeMaxDynamicSharedMemorySize, GSMEM);
    cudaFuncSetAttribute(attn_mma, cudaFuncAttributeMaxDynamicSharedMemorySize, ATT_SMEM);

    conv_all<<<2097152 / 256, 256>>>(x, w_qkv, w_out);

    // QKV: 24 n-tiles x 32 m-tiles (128x128)
    hmma_gemm<0><<<dim3(24, 32), 256, GSMEM>>>(nullptr, nullptr);

    // attention: 128-row q-tiles, 128 threads, 2 CTAs/SM
    attn_mma<<<dim3(L_ / 128, H_, B_), 128, ATT_SMEM>>>();

    // proj: 8 n-tiles x 32 m-tiles (128x128)
    hmma_gemm<1><<<dim3(8, 32), 256, GSMEM>>>(b_out, out);
}

// round 16
// speedup vs baseline: 1.2766x; 1.0202x over previous
#include <cuda_runtime.h>
#include <cuda_fp16.h>
#include <cstdint>

// ---------------------------------------------------------------------------
// MHA block. Round 16: GEMMs with 4-warp 64x64 warp tiles (128-thread CTAs);
// attention as round 15 (fp16 S accum, half2 softmax, Q-frag hoist).
// ---------------------------------------------------------------------------

#define B_   2
#define L_   2048
#define C_   1024
#define H_   16
#define DH_  64
#define QSCALE_ 0.045084439f   // 1024^-0.5 * log2(e)

// ---------------- scratch ----------------------------------------------------
__device__ __half g_x16[4096 * 1024];
__device__ __half g_wq16[3072 * 1024];
__device__ __half g_wo16[1024 * 1024];
__device__ __half g_at16[4096 * 1024];
__device__ __half g_qh[B_*H_*L_*DH_];
__device__ __half g_kh[B_*H_*L_*DH_];
__device__ __half g_vh[B_*H_*L_*DH_];

// ---------------- helpers ----------------------------------------------------
static __device__ __forceinline__ uint32_t smem_u32(const void* p) {
    uint32_t a;
    asm("{ .reg .u64 t; cvta.to.shared.u64 t, %1; cvt.u32.u64 %0, t; }"
        : "=r"(a) : "l"(p));
    return a;
}
#define SWZ(o)   ((o) ^ (((o) >> 3) & 0x70))   // 128B-row swizzle

static __device__ __forceinline__ void cp16(uint32_t saddr, const void* gaddr) {
    asm volatile("cp.async.cg.shared.global [%0], [%1], 16;"
                 :: "r"(saddr), "l"(gaddr) : "memory");
}
static __device__ __forceinline__ void ldmx4(uint32_t* r, uint32_t addr) {
    asm volatile("ldmatrix.sync.aligned.m8n8.x4.shared.b16 {%0,%1,%2,%3}, [%4];"
                 : "=r"(r[0]), "=r"(r[1]), "=r"(r[2]), "=r"(r[3]) : "r"(addr));
}
static __device__ __forceinline__ void ldmx4t(uint32_t* r, uint32_t addr) {
    asm volatile("ldmatrix.sync.aligned.m8n8.x4.trans.shared.b16 {%0,%1,%2,%3}, [%4];"
                 : "=r"(r[0]), "=r"(r[1]), "=r"(r[2]), "=r"(r[3]) : "r"(addr));
}
static __device__ __forceinline__ void mma16816h(float* c, const uint32_t* a,
                                                 const uint32_t* b) {
    asm volatile(
        "mma.sync.aligned.m16n8k16.row.col.f32.f16.f16.f32 "
        "{%0,%1,%2,%3}, {%4,%5,%6,%7}, {%8,%9}, {%0,%1,%2,%3};"
        : "+f"(c[0]), "+f"(c[1]), "+f"(c[2]), "+f"(c[3])
        : "r"(a[0]), "r"(a[1]), "r"(a[2]), "r"(a[3]), "r"(b[0]), "r"(b[1]));
}
// fp16-accumulator MMA (for S)
static __device__ __forceinline__ void mma16816hh(uint32_t* d, const uint32_t* a,
                                                  const uint32_t* b) {
    asm volatile(
        "mma.sync.aligned.m16n8k16.row.col.f16.f16.f16.f16 "
        "{%0,%1}, {%2,%3,%4,%5}, {%6,%7}, {%0,%1};"
        : "+r"(d[0]), "+r"(d[1])
        : "r"(a[0]), "r"(a[1]), "r"(a[2]), "r"(a[3]), "r"(b[0]), "r"(b[1]));
}
static __device__ __forceinline__ uint32_t packh(float a, float b) {
    __half2 t = __floats2half2_rn(a, b);
    return *reinterpret_cast<uint32_t*>(&t);
}
static __device__ __forceinline__ uint32_t ex2u(uint32_t p) {
    uint32_t r;
    asm("ex2.approx.f16x2 %0, %1;" : "=r"(r) : "r"(p));
    return r;
}
static __device__ __forceinline__ __half2 u2h(uint32_t u) {
    return *reinterpret_cast<__half2*>(&u);
}
static __device__ __forceinline__ uint32_t h2u(__half2 h) {
    return *reinterpret_cast<uint32_t*>(&h);
}

// ---------------------------------------------------------------------------
// Fused fp32 -> fp16 convert: x | w_qkv | w_out, one launch (float4 units).
// ---------------------------------------------------------------------------
__global__ __launch_bounds__(256) void conv_all(const float* __restrict__ x,
                                                const float* __restrict__ wq,
                                                const float* __restrict__ wo) {
    int i = blockIdx.x * 256 + threadIdx.x;
    const float* src;
    __half* dst;
    int off;
    if (i < 1048576)       { src = x;  dst = g_x16;  off = i; }
    else if (i < 1835008)  { src = wq; dst = g_wq16; off = i - 1048576; }
    else                   { src = wo; dst = g_wo16; off = i - 1835008; }
    float4 v = reinterpret_cast<const float4*>(src)[off];
    uint2 o;
    o.x = packh(v.x, v.y);
    o.y = packh(v.z, v.w);
    *reinterpret_cast<uint2*>(dst + (size_t)off * 4) = o;
}

// ---------------------------------------------------------------------------
// fp16 HMMA GEMM: 128x128 CTA tile, 4 warps (64x64 warp tiles), K-chunk 64
// (SW128), 3-stage, 2 CTAs/SM, one sync per chunk.
// OUTK 0: QKV -> q(scaled)/k/v fp16.  OUTK 1: out-proj fp32 + bias.
// ---------------------------------------------------------------------------
static constexpr int GSMEM = 98304;   // 3 stages x 32KB (A 16K | B 16K)

template <int OUTK>
__global__ __launch_bounds__(128, 2) void hmma_gemm(const float* __restrict__ bias,
                                                    float* __restrict__ outp) {
    extern __shared__ char smem[];
    const uint32_t sb = smem_u32(smem);
    const int tid = threadIdx.x;
    const int lane = tid & 31, wid = tid >> 5;     // 4 warps
    const int wm = wid & 1, wn = wid >> 1;         // 2x2 warp grid

    const __half* A  = (OUTK == 0) ? g_x16  : g_at16;
    const __half* Bm = (OUTK == 0) ? g_wq16 : g_wo16;

    const int n0 = blockIdx.x * 128;
    const int m0 = blockIdx.y * 128;
    const int part = (OUTK == 0) ? (blockIdx.x >> 3) : 0;     // 0=Q 1=K 2=V

    float c[4][8][4];   // [mi][nj][e] : warp 64x64
    #pragma unroll
    for (int i = 0; i < 4; i++)
        #pragma unroll
        for (int j = 0; j < 8; j++)
            #pragma unroll
            for (int e = 0; e < 4; e++) c[i][j][e] = 0.f;

    auto prefetch = [&](int ch) {
        const int s = ch % 3;
        const int k0 = ch * 64;
        #pragma unroll
        for (int p = 0; p < 2; p++) {
            const __half* src = p ? Bm : A;
            const int base = p ? n0 : m0;
            #pragma unroll
            for (int t = 0; t < 8; t++) {
                int idx = tid + t * 128;
                int r = idx >> 3, j = idx & 7;
                uint32_t sa = sb + s * 32768 + p * 16384 + SWZ(r * 128 + j * 16);
                cp16(sa, src + (size_t)(base + r) * 1024 + k0 + j * 8);
            }
        }
        asm volatile("cp.async.commit_group;" ::: "memory");
    };

    prefetch(0);
    prefetch(1);

    const int a_row = wm * 64 + (lane & 15);
    const int a_cb  = (lane >> 4) << 4;
    const int b_lr  = ((lane >> 4) << 3) + (lane & 7);
    const int b_cb  = ((lane >> 3) & 1) << 4;

    for (int ch = 0; ch < 16; ch++) {
        if (ch + 1 < 16) {
            asm volatile("cp.async.wait_group 1;" ::: "memory");
        } else {
            asm volatile("cp.async.wait_group 0;" ::: "memory");
        }
        __syncthreads();
        if (ch + 2 < 16) prefetch(ch + 2);

        const uint32_t stg = sb + (ch % 3) * 32768;
        const uint32_t aS = stg, bS = stg + 16384;

        #pragma unroll
        for (int ks = 0; ks < 4; ks++) {
            const int kb = ks * 32;
            uint32_t af[4][4];
            #pragma unroll
            for (int mi = 0; mi < 4; mi++)
                ldmx4(af[mi], aS + SWZ((a_row + mi * 16) * 128 + kb + a_cb));
            uint32_t bf[8][2];
            #pragma unroll
            for (int grp = 0; grp < 4; grp++) {
                uint32_t r[4];
                ldmx4(r, bS + SWZ((wn * 64 + grp * 16 + b_lr) * 128 + kb + b_cb));
                bf[grp * 2][0] = r[0]; bf[grp * 2][1] = r[1];
                bf[grp * 2 + 1][0] = r[2]; bf[grp * 2 + 1][1] = r[3];
            }
            #pragma unroll
            for (int mi = 0; mi < 4; mi++)
                #pragma unroll
                for (int nj = 0; nj < 8; nj++)
                    mma16816h(c[mi][nj], af[mi], bf[nj]);
        }
    }

    const int row_in = lane >> 2;
    const int col_in = (lane & 3) * 2;
    #pragma unroll
    for (int mi = 0; mi < 4; mi++) {
        #pragma unroll
        for (int nj = 0; nj < 8; nj++) {
            int o = n0 + wn * 64 + nj * 8 + col_in;
            #pragma unroll
            for (int half = 0; half < 2; half++) {
                int m = m0 + wm * 64 + mi * 16 + row_in + half * 8;
                float v0 = c[mi][nj][half * 2 + 0];
                float v1 = c[mi][nj][half * 2 + 1];
                if (OUTK == 0) {
                    int b = m >> 11, l = m & (L_ - 1);
                    int cc = o & (C_ - 1);
                    int hh = cc >> 6, d = cc & 63;
                    size_t base = (((size_t)(b << 4) + hh) * L_ + l) * DH_ + d;
                    if (part == 0) {
                        *reinterpret_cast<uint32_t*>(g_qh + base) =
                            packh(v0 * QSCALE_, v1 * QSCALE_);
                    } else if (part == 1) {
                        *reinterpret_cast<uint32_t*>(g_kh + base) = packh(v0, v1);
                    } else {
                        *reinterpret_cast<uint32_t*>(g_vh + base) = packh(v0, v1);
                    }
                } else {
                    float2* pd = reinterpret_cast<float2*>(outp + (size_t)m * C_ + o);
                    *pd = make_float2(v0 + bias[o], v1 + bias[o + 1]);
                }
            }
        }
    }
}

// ---------------------------------------------------------------------------
// Flash attention (round 15, best): 4 warps x 32 q-rows, Q frags hoisted,
// S accum fp16, half2 softmax in place, 4-stage KV, 2 CTAs/SM.
// smem: Q 16K | 4 x 16K = 80 KB.
// ---------------------------------------------------------------------------
static constexpr int ATT_KV   = 16384;
static constexpr int ATT_STG  = 16384;
static constexpr int ATT_SMEM = 81920;

__global__ __launch_bounds__(128, 2) void attn_mma() {
    extern __shared__ char smem[];
    const uint32_t sb = smem_u32(smem);
    const int tid = threadIdx.x, lane = tid & 31, w = tid >> 5;   // w: 0..3
    const int qt = blockIdx.x, h = blockIdx.y, b = blockIdx.z;
    const size_t bh = (size_t)(b * H_ + h) * L_;

    const int r0   = lane >> 2;
    const int cb   = (lane & 3) * 2;
    const int a_lr = lane & 15;
    const int a_cb = (lane >> 4) << 4;
    const int b_lr = ((lane >> 4) << 3) + (lane & 7);
    const int b_cb = ((lane >> 3) & 1) << 4;
    const int v_lr = (lane & 7) + (((lane >> 3) & 1) << 3);
    const int v_cB = ((lane >> 4) << 3) * 2;

    // ---- Q tile (128x64 fp16), once ----
    #pragma unroll
    for (int t = 0; t < 8; t++) {
        int idx = tid + t * 128;
        int r = idx >> 3, j = idx & 7;
        cp16(sb + SWZ(r * 128 + j * 16), g_qh + (bh + qt * 128 + r) * DH_ + j * 8);
    }
    asm volatile("cp.async.commit_group;" ::: "memory");

    auto prefetch = [&](int kt) {
        const uint32_t stg = sb + ATT_KV + (kt & 3) * ATT_STG;
        #pragma unroll
        for (int t = 0; t < 8; t++) {
            int idx = tid + t * 128;
            int p = idx >> 9, r = (idx >> 3) & 63, j = idx & 7;
            const __half* src = ((p == 0) ? g_kh : g_vh) + (bh + kt * 64 + r) * DH_ + j * 8;
            cp16(stg + p * 8192 + SWZ(r * 128 + j * 16), src);
        }
        asm volatile("cp.async.commit_group;" ::: "memory");
    };
    prefetch(0);
    prefetch(1);
    prefetch(2);

    // ---- hoist Q fragments to registers ----
    asm volatile("cp.async.wait_group 3;" ::: "memory");   // Q done (3 KV pending)
    __syncthreads();
    uint32_t qa[2][4][4];   // [mi][ks][frag]
    #pragma unroll
    for (int mi = 0; mi < 2; mi++)
        #pragma unroll
        for (int ks = 0; ks < 4; ks++)
            ldmx4(qa[mi][ks],
                  sb + SWZ((w * 32 + mi * 16 + a_lr) * 128 + ks * 32 + a_cb));

    float c_o[2][8][4];
    #pragma unroll
    for (int mi = 0; mi < 2; mi++)
        #pragma unroll
        for (int nj = 0; nj < 8; nj++)
            #pragma unroll
            for (int e = 0; e < 4; e++) c_o[mi][nj][e] = 0.f;
    float m2[2][2] = {{-1e30f, -1e30f}, {-1e30f, -1e30f}};
    float l2[2][2] = {{0.f, 0.f}, {0.f, 0.f}};

    const int NKT = L_ / 64;
    for (int kt = 0; kt < NKT; kt++) {
        int inflight = (NKT - 1 - kt < 2) ? (NKT - 1 - kt) : 2;
        if (inflight == 2) {
            asm volatile("cp.async.wait_group 2;" ::: "memory");
        } else if (inflight == 1) {
            asm volatile("cp.async.wait_group 1;" ::: "memory");
        } else {
            asm volatile("cp.async.wait_group 0;" ::: "memory");
        }
        __syncthreads();
        if (kt + 3 < NKT) prefetch(kt + 3);

        const uint32_t stg = sb + ATT_KV + (kt & 3) * ATT_STG;
        const uint32_t kH = stg, vH = stg + 8192;

        // ---- S = Q K^T : fp16 accumulators ----
        uint32_t sp[2][8][2];
        #pragma unroll
        for (int mi = 0; mi < 2; mi++)
            #pragma unroll
            for (int nj = 0; nj < 8; nj++)
                sp[mi][nj][0] = sp[mi][nj][1] = 0u;

        #pragma unroll
        for (int ks = 0; ks < 4; ks++) {
            const int kb = ks * 32;
            #pragma unroll
            for (int grp = 0; grp < 4; grp++) {
                uint32_t off = SWZ((grp * 16 + b_lr) * 128 + kb + b_cb);
                uint32_t r[4];
                ldmx4(r, kH + off);
                uint32_t f0[2] = {r[0], r[1]}, f1[2] = {r[2], r[3]};
                #pragma unroll
                for (int mi = 0; mi < 2; mi++) {
                    mma16816hh(sp[mi][grp * 2],     qa[mi][ks], f0);
                    mma16816hh(sp[mi][grp * 2 + 1], qa[mi][ks], f1);
                }
            }
        }

        // ---- half2 online softmax; sp -> P frags in place ----
        #pragma unroll
        for (int mi = 0; mi < 2; mi++) {
            #pragma unroll
            for (int rh = 0; rh < 2; rh++) {
                __half2 mx2 = u2h(sp[mi][0][rh]);
                #pragma unroll
                for (int nj = 1; nj < 8; nj++)
                    mx2 = __hmax2(mx2, u2h(sp[mi][nj][rh]));
                float mx = fmaxf(__low2float(mx2), __high2float(mx2));
                mx = fmaxf(mx, __shfl_xor_sync(0xffffffffu, mx, 1));
                mx = fmaxf(mx, __shfl_xor_sync(0xffffffffu, mx, 2));
                float mnew = fmaxf(m2[mi][rh], mx);
                float alpha = exp2f(m2[mi][rh] - mnew);
                m2[mi][rh] = mnew;

                __half2 mh = __float2half2_rn(mnew);
                __half2 ssum = __float2half2_rn(0.f);
                #pragma unroll
                for (int nj = 0; nj < 8; nj++) {
                    uint32_t e = ex2u(h2u(__hsub2(u2h(sp[mi][nj][rh]), mh)));
                    sp[mi][nj][rh] = e;
                    ssum = __hadd2(ssum, u2h(e));
                }
                float rs = __low2float(ssum) + __high2float(ssum);
                rs += __shfl_xor_sync(0xffffffffu, rs, 1);
                rs += __shfl_xor_sync(0xffffffffu, rs, 2);
                l2[mi][rh] = l2[mi][rh] * alpha + rs;
                #pragma unroll
                for (int nj = 0; nj < 8; nj++) {
                    c_o[mi][nj][rh * 2]     *= alpha;
                    c_o[mi][nj][rh * 2 + 1] *= alpha;
                }
            }
        }

        // ---- O += P V ----
        #pragma unroll
        for (int ks = 0; ks < 4; ks++) {
            uint32_t vb[8][2];
            #pragma unroll
            for (int grp = 0; grp < 4; grp++) {
                uint32_t off = SWZ((ks * 16 + v_lr) * 128 + grp * 32 + v_cB);
                uint32_t r[4];
                ldmx4t(r, vH + off);
                vb[grp * 2][0] = r[0]; vb[grp * 2][1] = r[1];
                vb[grp * 2 + 1][0] = r[2]; vb[grp * 2 + 1][1] = r[3];
            }
            #pragma unroll
            for (int mi = 0; mi < 2; mi++) {
                uint32_t pa[4] = {sp[mi][ks * 2][0], sp[mi][ks * 2][1],
                                  sp[mi][ks * 2 + 1][0], sp[mi][ks * 2 + 1][1]};
                #pragma unroll
                for (int nj = 0; nj < 8; nj++)
                    mma16816h(c_o[mi][nj], pa, vb[nj]);
            }
        }
    }

    // ---- epilogue: O/l -> fp16 att ----
    #pragma unroll
    for (int mi = 0; mi < 2; mi++)
        #pragma unroll
        for (int rh = 0; rh < 2; rh++) {
            int row = qt * 128 + w * 32 + mi * 16 + r0 + rh * 8;
            float inv = 1.0f / l2[mi][rh];
            size_t grow = ((size_t)b * L_ + row) * C_ + h * DH_;
            #pragma unroll
            for (int nj = 0; nj < 8; nj++) {
                float o0 = c_o[mi][nj][rh * 2]     * inv;
                float o1 = c_o[mi][nj][rh * 2 + 1] * inv;
                *reinterpret_cast<uint32_t*>(g_at16 + grow + nj * 8 + cb) = packh(o0, o1);
            }
        }
}

// ---------------------------------------------------------------------------
extern "C" void kernel_launch(void* const* d_in, const int* in_sizes, int n_in,
                              void* d_out, int out_size) {
    const float* x     = (const float*)d_in[0];
    const float* w_qkv = (const float*)d_in[1];
    const float* w_out = (const float*)d_in[2];
    const float* b_out = (const float*)d_in[3];
    float* out = (float*)d_out;

    cudaFuncSetAttribute(hmma_gemm<0>, cudaFuncAttributeMaxDynamicSharedMemorySize, GSMEM);
    cudaFuncSetAttribute(hmma_gemm<1>, cudaFuncAttributeMaxDynamicSharedMemorySize, GSMEM);
    cudaFuncSetAttribute(attn_mma, cudaFuncAttributeMaxDynamicSharedMemorySize, ATT_SMEM);

    conv_all<<<2097152 / 256, 256>>>(x, w_qkv, w_out);

    // QKV: 24 n-tiles x 32 m-tiles (128x128), 128 threads
    hmma_gemm<0><<<dim3(24, 32), 128, GSMEM>>>(nullptr, nullptr);

    // attention: 128-row q-tiles, 128 threads, 2 CTAs/SM
    attn_mma<<<dim3(L_ / 128, H_, B_), 128, ATT_SMEM>>>();

    // proj: 8 n-tiles x 32 m-tiles (128x128), 128 threads
    hmma_gemm<1><<<dim3(8, 32), 128, GSMEM>>>(b_out, out);
}